// round 4
// baseline (speedup 1.0000x reference)
#include <cuda_runtime.h>
#include <math.h>

#define D 256
#define HALF_D 128
#define MAXN 4096

// ---- device scratch (module-load zero-initialized; no allocations) ----
__device__ float g_M [D*D];   // dense skew: M[r][c]=+s, M[c][r]=-s (non-edges stay 0 forever)
__device__ float g_M2[D*D];   // M^2
__device__ float g_M4[D*D];   // M^4
__device__ float g_V [D*D];   // V = (M+M^2)(I+M^2)
__device__ float g_G [D*D];   // G = 2 V (I+M^4)  = R - I   (powers M^1..M^8)
__device__ float2 g_cs[MAXN*HALF_D]; // (cos,sin) per (position, freq-pair)

// packed-f32x2 helpers (Blackwell f32x2 pipe, PTX-only)
#define FMA2(d, a, b) asm("fma.rn.f32x2 %0, %1, %2, %0;" : "+l"(d) : "l"(a), "l"(b))
#define DUP2(d, f)    asm("mov.b64 %0, {%1, %1};" : "=l"(d) : "r"(__float_as_uint(f)))

// ---------------- fused front: edge scatter + cos/sin table ----------------
__global__ void k_front(const int* __restrict__ rows, const int* __restrict__ cols,
                        const float* __restrict__ s, int E,
                        const int* __restrict__ pos, const float* __restrict__ freqs, int N) {
    int idx = blockIdx.x * blockDim.x + threadIdx.x;
    int tableN = N * HALF_D;
    if (idx < tableN) {
        int n = idx >> 7, j = idx & (HALF_D - 1);
        float ang = (float)pos[n] * freqs[j];          // fp32 rounding matches ref
        double a  = (double)ang;                       // exact range reduction
        double qd = rint(a * 0.15915494309189535);
        double rd = a - qd * 6.283185307179586477;
        float rf  = (float)rd;
        g_cs[idx] = make_float2(__cosf(rf), __sinf(rf));
    } else {
        int e = idx - tableN;
        if (e < E) {
            int r = rows[e], c = cols[e];
            float v = s[e];
            g_M[r*D + c] =  v;     // idempotent each replay
            g_M[c*D + r] = -v;
        }
    }
}

// ---------------- tiled 256x256 matmuls for the Cayley prep chain ----------------
// 4 rows per block (A rows staged in shared, broadcast reads); thread j owns col j.
// step 0 (grid  64): M2 = M * M
// step 1 (grid 128): bx<64 : V  = U + U*M2,  U = M+M2  (U rows built in shared)
//                    bx>=64: M4 = M2 * M2
// step 2 (grid  64): G  = 2*(V + V*M4)
__global__ void __launch_bounds__(256) k_dmm(int step) {
    __shared__ float As[4][D];
    int j  = threadIdx.x;
    int bx = blockIdx.x;

    const float* Bm;
    float* outp;
    int   r0;
    float addSelf, scale;   // out = scale*(acc + addSelf*As_row)

    if (step == 0) {
        r0 = bx * 4; Bm = g_M;  outp = g_M2; addSelf = 0.f; scale = 1.f;
        #pragma unroll
        for (int r = 0; r < 4; r++) As[r][j] = g_M[(size_t)(r0 + r)*D + j];
    } else if (step == 1) {
        if (bx < 64) {
            r0 = bx * 4; Bm = g_M2; outp = g_V; addSelf = 1.f; scale = 1.f;
            #pragma unroll
            for (int r = 0; r < 4; r++)
                As[r][j] = g_M[(size_t)(r0 + r)*D + j] + g_M2[(size_t)(r0 + r)*D + j];
        } else {
            r0 = (bx - 64) * 4; Bm = g_M2; outp = g_M4; addSelf = 0.f; scale = 1.f;
            #pragma unroll
            for (int r = 0; r < 4; r++) As[r][j] = g_M2[(size_t)(r0 + r)*D + j];
        }
    } else {
        r0 = bx * 4; Bm = g_M4; outp = g_G; addSelf = 1.f; scale = 2.f;
        #pragma unroll
        for (int r = 0; r < 4; r++) As[r][j] = g_V[(size_t)(r0 + r)*D + j];
    }
    __syncthreads();

    float acc0 = 0.f, acc1 = 0.f, acc2 = 0.f, acc3 = 0.f;
    #pragma unroll 8
    for (int k = 0; k < D; k++) {
        float b = Bm[(size_t)k*D + j];
        acc0 = fmaf(As[0][k], b, acc0);
        acc1 = fmaf(As[1][k], b, acc1);
        acc2 = fmaf(As[2][k], b, acc2);
        acc3 = fmaf(As[3][k], b, acc3);
    }

    outp[(size_t)(r0+0)*D + j] = scale * (acc0 + addSelf * As[0][j]);
    outp[(size_t)(r0+1)*D + j] = scale * (acc1 + addSelf * As[1][j]);
    outp[(size_t)(r0+2)*D + j] = scale * (acc2 + addSelf * As[2][j]);
    outp[(size_t)(r0+3)*D + j] = scale * (acc3 + addSelf * As[3][j]);
}

// ---------------- main GEMM: out = H + H*G, RoPE fused into A-tile load ----------------
// Block: 256 threads, tile 16 rows x 256 cols. Accumulators packed over ROW PAIRS
// in f32x2; G scalar duplicated once per (k, col).
__global__ void __launch_bounds__(256) k_gemm(const float* __restrict__ q,
                                              const float* __restrict__ kk,
                                              float* __restrict__ out,
                                              int BN, int N) {
    __shared__ __align__(16) float2 As2[8][D];   // [rowpair p][k] = (row 2p, row 2p+1)
    int t = threadIdx.x;
    int row0 = blockIdx.x * 16;

    // Fill A-tile with RoPE applied on the fly.
    for (int idx = t; idx < 16 * HALF_D; idx += 256) {
        int r  = idx >> 7;          // row within tile
        int jp = idx & (HALF_D-1);  // rotation pair
        int row = row0 + r;
        const float* src; int n;
        if (row < BN) { src = q  + (size_t)row*D;      n = row % N; }
        else          { src = kk + (size_t)(row-BN)*D; n = (row-BN) % N; }
        float2 v  = *(const float2*)(src + 2*jp);
        float2 cs = g_cs[n*HALF_D + jp];
        float e = v.x*cs.x - v.y*cs.y;
        float o = v.x*cs.y + v.y*cs.x;
        float* As2f = (float*)As2;
        int base = ((r >> 1)*D + 2*jp)*2 + (r & 1);
        As2f[base]     = e;
        As2f[base + 2] = o;
    }
    __syncthreads();

    int cg = t & 127;          // column group (2 cols)
    int rg = t >> 7;           // row group (8 rows)
    int j0 = cg * 2;
    int p0 = rg * 4;

    unsigned long long acc[4][2];
    #pragma unroll
    for (int pp = 0; pp < 4; pp++) { acc[pp][0] = 0ull; acc[pp][1] = 0ull; }

    #pragma unroll 8
    for (int k = 0; k < D; k += 2) {
        float2 gk0 = *(const float2*)&g_G[(size_t)k*D + j0];
        float2 gk1 = *(const float2*)&g_G[(size_t)(k+1)*D + j0];
        unsigned long long g00, g01, g10, g11;
        DUP2(g00, gk0.x); DUP2(g01, gk0.y);
        DUP2(g10, gk1.x); DUP2(g11, gk1.y);
        ulonglong2 Ap[4];
        #pragma unroll
        for (int pp = 0; pp < 4; pp++)
            Ap[pp] = *(const ulonglong2*)&As2[p0 + pp][k];
        #pragma unroll
        for (int pp = 0; pp < 4; pp++) {
            FMA2(acc[pp][0], Ap[pp].x, g00);
            FMA2(acc[pp][1], Ap[pp].x, g01);
            FMA2(acc[pp][0], Ap[pp].y, g10);
            FMA2(acc[pp][1], Ap[pp].y, g11);
        }
    }

    // Epilogue: out = H + correction. acc[pp][c] packs (even row, odd row) for
    // column j0+c; regroup into per-row float2 (cols j0, j0+1 contiguous) -> STG.64.
    #pragma unroll
    for (int pp = 0; pp < 4; pp++) {
        int p  = p0 + pp;
        int re = row0 + 2*p;
        float2 h0 = As2[p][j0];       // (even row, odd row) of col j0
        float2 h1 = As2[p][j0 + 1];   // (even row, odd row) of col j0+1
        unsigned long long a0 = acc[pp][0], a1 = acc[pp][1];
        float2 oe, oo;
        oe.x = h0.x + __uint_as_float((unsigned)a0);
        oe.y = h1.x + __uint_as_float((unsigned)a1);
        oo.x = h0.y + __uint_as_float((unsigned)(a0 >> 32));
        oo.y = h1.y + __uint_as_float((unsigned)(a1 >> 32));
        *(float2*)&out[(size_t)re*D     + j0] = oe;
        *(float2*)&out[(size_t)(re+1)*D + j0] = oo;
    }
}

// ---------------- launcher: 5 launches total ----------------
extern "C" void kernel_launch(void* const* d_in, const int* in_sizes, int n_in,
                              void* d_out, int out_size) {
    const float* q     = (const float*)d_in[0];
    const float* k     = (const float*)d_in[1];
    const float* freqs = (const float*)d_in[2];
    const float* sp    = (const float*)d_in[3];
    const int*   pos   = (const int*)  d_in[4];
    const int*   rows  = (const int*)  d_in[5];
    const int*   cols  = (const int*)  d_in[6];
    float* out = (float*)d_out;

    int E    = in_sizes[3];
    int N    = in_sizes[4];
    int BN   = in_sizes[0] / D;   // rows of q (= B*N)
    int ROWS = 2 * BN;

    int frontWork = N*HALF_D + E;
    k_front<<<(frontWork + 255)/256, 256>>>(rows, cols, sp, E, pos, freqs, N);

    k_dmm<<< 64, 256>>>(0);   // M2 = M*M
    k_dmm<<<128, 256>>>(1);   // V = (M+M2)(I+M2)  and  M4 = M2*M2
    k_dmm<<< 64, 256>>>(2);   // G = 2 V (I+M4)

    k_gemm<<<ROWS/16, 256>>>(q, k, out, BN, N);
}

// round 5
// speedup vs baseline: 1.3039x; 1.3039x over previous
#include <cuda_runtime.h>
#include <math.h>

#define D 256
#define HALF_D 128
#define MAXN 4096

// ---- device scratch (module-load zero-initialized; no allocations) ----
__device__ float g_M [D*D];   // dense skew: M[r][c]=+s, M[c][r]=-s (non-edges stay 0 forever)
__device__ float g_M2[D*D];   // M^2
__device__ float g_M4[D*D];   // M^4
__device__ float g_Y [D*D];   // Y = (M+M^2)(I+M^2) = M+M^2+M^3+M^4
__device__ float g_G [D*D];   // G = 2 Y (I+M^4) = 2(M+..+M^8) ~= R - I
__device__ float2 g_cs[MAXN*HALF_D]; // (cos,sin) per (position, freq-pair)

// packed-f32x2 helpers (Blackwell f32x2 pipe, PTX-only)
#define FMA2(d, a, b) asm("fma.rn.f32x2 %0, %1, %2, %0;" : "+l"(d) : "l"(a), "l"(b))
#define DUP2(d, f)    asm("mov.b64 %0, {%1, %1};" : "=l"(d) : "r"(__float_as_uint(f)))

// ---------------- fused front: edge scatter + cos/sin table (all fp32) ----------------
__global__ void k_front(const int* __restrict__ rows, const int* __restrict__ cols,
                        const float* __restrict__ s, int E,
                        const int* __restrict__ pos, const float* __restrict__ freqs, int N) {
    int idx = blockIdx.x * blockDim.x + threadIdx.x;
    int tableN = N * HALF_D;
    if (idx < tableN) {
        int n = idx >> 7, j = idx & (HALF_D - 1);
        float ang = (float)pos[n] * freqs[j];          // fp32 rounding matches ref
        // 2-term Cody-Waite range reduction, all fp32 (|ang| <= ~4096, q <= ~652)
        const float INV2PI = 0.15915494309189535f;
        const float C1 = 6.2831854820251465f;          // float(2*pi)
        const float C2 = -1.7484556000744263e-7f;      // 2*pi - (double)C1
        float q = rintf(ang * INV2PI);
        float r = fmaf(-q, C1, ang);
        r = fmaf(-q, C2, r);                           // |r| <= pi + ~1e-5, err ~2e-7
        g_cs[idx] = make_float2(__cosf(r), __sinf(r));
    } else {
        int e = idx - tableN;
        if (e < E) {
            int r = rows[e], c = cols[e];
            float v = s[e];
            g_M[r*D + c] =  v;     // idempotent each replay
            g_M[c*D + r] = -v;
        }
    }
}

// ---------------- dense 256x256 matmul steps for the Cayley prep chain ----------------
// 512 threads: p = tid>>8 (row within 2-row tile), j = tid&255 (column).
// Both p-halves read the same streamed-B address -> L1 broadcast.
// Explicit 8-wide load batches guarantee MLP independent of ptxas reg choices.
// step 0 (grid 128): M2 = M*M
// step 1 (grid 256): bx<128: Y = X + X*M2 (X = M+M2); bx>=128: M4 = M2*M2
// step 2 (grid 128): G = 2*(Y + Y*M4)
__global__ void k_dmm(int step) {
    __shared__ float As[2][D];
    int tid = threadIdx.x;
    int p = tid >> 8;
    int j = tid & 255;
    int bx = blockIdx.x;

    const float* Bm;
    float* outp;
    int r0;
    float selfw, scale;    // out = scale*(acc + selfw*As[p][j])

    if (step == 0) {
        r0 = bx*2; Bm = g_M2; // placeholder, fixed below
        Bm = g_M;  outp = g_M2; selfw = 0.f; scale = 1.f;
        As[p][j] = g_M[(r0 + p)*D + j];
    } else if (step == 1) {
        if (bx < 128) {
            r0 = bx*2; Bm = g_M2; outp = g_Y; selfw = 1.f; scale = 1.f;
            As[p][j] = g_M[(r0 + p)*D + j] + g_M2[(r0 + p)*D + j];   // X = M + M^2
        } else {
            r0 = (bx-128)*2; Bm = g_M2; outp = g_M4; selfw = 0.f; scale = 1.f;
            As[p][j] = g_M2[(r0 + p)*D + j];
        }
    } else {
        r0 = bx*2; Bm = g_M4; outp = g_G; selfw = 1.f; scale = 2.f;
        As[p][j] = g_Y[(r0 + p)*D + j];
    }
    __syncthreads();

    float acc = 0.f;
    #pragma unroll 4
    for (int k = 0; k < D; k += 8) {
        float b[8];
        #pragma unroll
        for (int u = 0; u < 8; u++) b[u] = Bm[(k + u)*D + j];   // 8 independent LDGs
        #pragma unroll
        for (int u = 0; u < 8; u++) acc = fmaf(As[p][k + u], b[u], acc);
    }

    outp[(r0 + p)*D + j] = scale * (acc + selfw * As[p][j]);
}

// ---------------- main GEMM: out = H + H*G, RoPE fused into A-tile load ----------------
// Block: 256 threads, tile 16 rows x 256 cols. Accumulators packed over ROW PAIRS
// in f32x2; G scalar duplicated once per (k, col).
__global__ void __launch_bounds__(256) k_gemm(const float* __restrict__ q,
                                              const float* __restrict__ kk,
                                              float* __restrict__ out,
                                              int BN, int N) {
    __shared__ __align__(16) float2 As2[8][D];   // [rowpair p][k] = (row 2p, row 2p+1)
    int t = threadIdx.x;
    int row0 = blockIdx.x * 16;

    // Fill A-tile with RoPE applied on the fly.
    for (int idx = t; idx < 16 * HALF_D; idx += 256) {
        int r  = idx >> 7;          // row within tile
        int jp = idx & (HALF_D-1);  // rotation pair
        int row = row0 + r;
        const float* src; int n;
        if (row < BN) { src = q  + (size_t)row*D;      n = row % N; }
        else          { src = kk + (size_t)(row-BN)*D; n = (row-BN) % N; }
        float2 v  = *(const float2*)(src + 2*jp);
        float2 cs = g_cs[n*HALF_D + jp];
        float e = v.x*cs.x - v.y*cs.y;
        float o = v.x*cs.y + v.y*cs.x;
        float* As2f = (float*)As2;
        int base = ((r >> 1)*D + 2*jp)*2 + (r & 1);
        As2f[base]     = e;
        As2f[base + 2] = o;
    }
    __syncthreads();

    int cg = t & 127;          // column group (2 cols)
    int rg = t >> 7;           // row group (8 rows)
    int j0 = cg * 2;
    int p0 = rg * 4;

    unsigned long long acc[4][2];
    #pragma unroll
    for (int pp = 0; pp < 4; pp++) { acc[pp][0] = 0ull; acc[pp][1] = 0ull; }

    #pragma unroll 8
    for (int k = 0; k < D; k += 2) {
        float2 gk0 = *(const float2*)&g_G[(size_t)k*D + j0];
        float2 gk1 = *(const float2*)&g_G[(size_t)(k+1)*D + j0];
        unsigned long long g00, g01, g10, g11;
        DUP2(g00, gk0.x); DUP2(g01, gk0.y);
        DUP2(g10, gk1.x); DUP2(g11, gk1.y);
        ulonglong2 Ap[4];
        #pragma unroll
        for (int pp = 0; pp < 4; pp++)
            Ap[pp] = *(const ulonglong2*)&As2[p0 + pp][k];
        #pragma unroll
        for (int pp = 0; pp < 4; pp++) {
            FMA2(acc[pp][0], Ap[pp].x, g00);
            FMA2(acc[pp][1], Ap[pp].x, g01);
            FMA2(acc[pp][0], Ap[pp].y, g10);
            FMA2(acc[pp][1], Ap[pp].y, g11);
        }
    }

    // Epilogue: out = H + correction; regroup packed row-pairs into per-row STG.64.
    #pragma unroll
    for (int pp = 0; pp < 4; pp++) {
        int p  = p0 + pp;
        int re = row0 + 2*p;
        float2 h0 = As2[p][j0];
        float2 h1 = As2[p][j0 + 1];
        unsigned long long a0 = acc[pp][0], a1 = acc[pp][1];
        float2 oe, oo;
        oe.x = h0.x + __uint_as_float((unsigned)a0);
        oe.y = h1.x + __uint_as_float((unsigned)a1);
        oo.x = h0.y + __uint_as_float((unsigned)(a0 >> 32));
        oo.y = h1.y + __uint_as_float((unsigned)(a1 >> 32));
        *(float2*)&out[(size_t)re*D     + j0] = oe;
        *(float2*)&out[(size_t)(re+1)*D + j0] = oo;
    }
}

// ---------------- launcher: 5 launches total ----------------
extern "C" void kernel_launch(void* const* d_in, const int* in_sizes, int n_in,
                              void* d_out, int out_size) {
    const float* q     = (const float*)d_in[0];
    const float* k     = (const float*)d_in[1];
    const float* freqs = (const float*)d_in[2];
    const float* sp    = (const float*)d_in[3];
    const int*   pos   = (const int*)  d_in[4];
    const int*   rows  = (const int*)  d_in[5];
    const int*   cols  = (const int*)  d_in[6];
    float* out = (float*)d_out;

    int E    = in_sizes[3];
    int N    = in_sizes[4];
    int BN   = in_sizes[0] / D;   // rows of q (= B*N)
    int ROWS = 2 * BN;

    int frontWork = N*HALF_D + E;
    k_front<<<(frontWork + 255)/256, 256>>>(rows, cols, sp, E, pos, freqs, N);

    k_dmm<<<128, 512>>>(0);   // M2 = M*M
    k_dmm<<<256, 512>>>(1);   // Y = (M+M2)(I+M2)  and  M4 = M2*M2
    k_dmm<<<128, 512>>>(2);   // G = 2 Y (I+M4)

    k_gemm<<<ROWS/16, 256>>>(q, k, out, BN, N);
}